// round 13
// baseline (speedup 1.0000x reference)
#include <cuda_runtime.h>
#include <cuda_fp16.h>
#include <stdint.h>
#include <math.h>

#define NB   2048
#define NT   64
#define NL   8
#define NH   64
#define NSEQ (NB*NL)          // 16384
#define RPC  64               // rows per GRU CTA
#define GCTA (NSEQ/RPC)       // 256 CTAs
#define GT   256              // GRU threads per CTA

// ---- SMEM map for GRU mainloop (bytes) -------------------------------------
#define SO_B2   0
#define SO_B4   16384
#define SO_BK2  32768
#define SO_BK4  36864
#define SO_A    45056
#define SMEMSZ  65536

// ---- scratch (__device__ globals; allocs forbidden) -----------------------
__device__ __align__(16) float g_hidden[NSEQ * NH];   // [seq][64]
__device__ __align__(16) char g_Ball[45056];          // packed B regions
__device__ __align__(16) float g_yc[NL * 7 * 20];     // relu(ce@Wcc^T+bcc)

__device__ __forceinline__ float sigf(float x) {
    return __fdividef(1.0f, 1.0f + __expf(-x));
}
__device__ __forceinline__ float tanha(float x) {
    float y;
    asm("tanh.approx.f32 %0, %1;" : "=f"(y) : "f"(x));
    return y;
}
__device__ __forceinline__ float siga(float x) {     // sigmoid via tanh, 1 MUFU
    return fmaf(0.5f, tanha(0.5f * x), 0.5f);
}
__device__ __forceinline__ uint32_t h2bits(float a, float b) {
    __half2 h = __floats2half2_rn(a, b);
    return *reinterpret_cast<uint32_t*>(&h);
}

// mma.sync m16n8k16 f16 -> f32 accumulate
__device__ __forceinline__ void hmma(float c[4], const uint4& a,
                                     uint32_t b0, uint32_t b1) {
    asm("mma.sync.aligned.m16n8k16.row.col.f32.f16.f16.f32 "
        "{%0,%1,%2,%3},{%4,%5,%6,%7},{%8,%9},{%0,%1,%2,%3};"
        : "+f"(c[0]), "+f"(c[1]), "+f"(c[2]), "+f"(c[3])
        : "r"(a.x), "r"(a.y), "r"(a.z), "r"(a.w), "r"(b0), "r"(b1));
}

__constant__ int c_PL[8][2] = {{1,3},{0,2},{5,7},{4,6},{0,1},{2,3},{4,5},{6,7}};

// ---------------------------------------------------------------------------
// Kernel 0: pack weights + yc table, one launch.
// gates g: 0=r, 1=z, 2=ghn, 3=gin
// ---------------------------------------------------------------------------
__device__ __forceinline__ float b4val(int g, int nl, int k,
                                       const float* Wih, const float* bih,
                                       const float* bhh) {
    if (k < 4) {
        if (g == 0) return Wih[nl * 4 + k];
        if (g == 1) return Wih[(64 + nl) * 4 + k];
        if (g == 2) return 0.0f;
        return Wih[(128 + nl) * 4 + k];
    }
    if (k == 4) {
        if (g == 0) return bih[nl] + bhh[nl];
        if (g == 1) return bih[64 + nl] + bhh[64 + nl];
        if (g == 2) return bhh[128 + nl];
        return bih[128 + nl];
    }
    return 0.0f;
}

__global__ void build_tables(const float* __restrict__ Wih, const float* __restrict__ Whh,
                             const float* __restrict__ bih, const float* __restrict__ bhh,
                             const int* __restrict__ relation,
                             const float* __restrict__ emb_const,
                             const float* __restrict__ Wcc,
                             const float* __restrict__ bcc)
{
    int i = blockIdx.x * blockDim.x + threadIdx.x;
    if (i >= 4096) {
        int j = i - 4096;
        if (j < NL * 7 * 20) {
            int o = j % 20, pq = j / 20;
            int p = pq / 7, q = pq % 7;
            const float* ce = emb_const + relation[p * 7 + q] * 4;
            float v = bcc[o];
#pragma unroll
            for (int c = 0; c < 4; c++) v = fmaf(ce[c], Wcc[o * 4 + c], v);
            g_yc[j] = fmaxf(v, 0.0f);
        }
        return;
    }
    int lane = i & 31;
    float w[4];
    char* dst;
    bool wide;

    if (i < 2048) {                       // B2: Whh r,z hi-only
        int tile = i >> 5;
        int kt = tile & 3, nt16 = tile >> 2;
        int g = nt16 >> 3, nb = nt16 & 7;
        int row = g * 64 + nb * 8 + (lane >> 2);
        int k0 = kt * 16 + 2 * (lane & 3);
        w[0] = Whh[row*64 + k0];     w[1] = Whh[row*64 + k0 + 1];
        w[2] = Whh[row*64 + k0 + 8]; w[3] = Whh[row*64 + k0 + 9];
        dst = g_Ball + SO_B2 + tile * 256 + lane * 8;  wide = false;
    } else if (i < 3072) {                // B4: Whh ghn hi/lo
        int idx = i - 2048, tile = idx >> 5;
        int kt = tile & 3, nt8 = tile >> 2;
        int row = 128 + nt8 * 8 + (lane >> 2);
        int k0 = kt * 16 + 2 * (lane & 3);
        w[0] = Whh[row*64 + k0];     w[1] = Whh[row*64 + k0 + 1];
        w[2] = Whh[row*64 + k0 + 8]; w[3] = Whh[row*64 + k0 + 9];
        dst = g_Ball + SO_B4 + tile * 512 + lane * 16; wide = true;
    } else if (i < 3584) {                // BK2: kt4 r,z hi-only
        int idx = i - 3072, tile = idx >> 5;
        int g = tile >> 3, nb = tile & 7;
        int nl = nb * 8 + (lane >> 2);
        int k0 = 2 * (lane & 3);
        w[0] = b4val(g, nl, k0,     Wih, bih, bhh);
        w[1] = b4val(g, nl, k0 + 1, Wih, bih, bhh);
        w[2] = b4val(g, nl, k0 + 8, Wih, bih, bhh);
        w[3] = b4val(g, nl, k0 + 9, Wih, bih, bhh);
        dst = g_Ball + SO_BK2 + tile * 256 + lane * 8; wide = false;
    } else {                              // BK4: kt4 ghn,gin hi/lo
        int idx = i - 3584, tile = idx >> 5;
        int g = 2 + (tile >> 3), nb = tile & 7;
        int nl = nb * 8 + (lane >> 2);
        int k0 = 2 * (lane & 3);
        w[0] = b4val(g, nl, k0,     Wih, bih, bhh);
        w[1] = b4val(g, nl, k0 + 1, Wih, bih, bhh);
        w[2] = b4val(g, nl, k0 + 8, Wih, bih, bhh);
        w[3] = b4val(g, nl, k0 + 9, Wih, bih, bhh);
        dst = g_Ball + SO_BK4 + tile * 512 + lane * 16; wide = true;
    }

    __half hi[4], lo[4];
#pragma unroll
    for (int q = 0; q < 4; q++) {
        hi[q] = __float2half_rn(w[q]);
        lo[q] = __float2half_rn(w[q] - __half2float(hi[q]));
    }
    uint2 vh;
    { __half2 p(hi[0], hi[1]); vh.x = *reinterpret_cast<uint32_t*>(&p); }
    { __half2 p(hi[2], hi[3]); vh.y = *reinterpret_cast<uint32_t*>(&p); }
    *(uint2*)dst = vh;
    if (wide) {
        uint2 vl;
        { __half2 p(lo[0], lo[1]); vl.x = *reinterpret_cast<uint32_t*>(&p); }
        { __half2 p(lo[2], lo[3]); vl.y = *reinterpret_cast<uint32_t*>(&p); }
        *(uint2*)(dst + 8) = vl;
    }
}

// ---------------------------------------------------------------------------
// Kernel 2: tensor-core GRU (R7's proven mainloop — unchanged).
// ---------------------------------------------------------------------------
__global__ void __launch_bounds__(GT, 2)
gru_kernel(const float* __restrict__ hist,
           const float* __restrict__ Wh,
           const float* __restrict__ bh)
{
    extern __shared__ char smem[];
    __shared__ float sW[16];   // [0..11]=Wh, [12..15]=bh
    const int tid = threadIdx.x;
    const int l   = tid & 31;
    const int wid = tid >> 5;
    const int mg  = wid >> 2;
    const int ng  = wid & 3;
    const int gtid = tid & 127;
    const int c4  = l & 3;
    const int lr  = l >> 2;
    const int seq0 = blockIdx.x * RPC;

    {
        const uint4* src = (const uint4*)g_Ball;
        uint4* dst = (uint4*)smem;
        for (int i = tid; i < 45056 / 16; i += GT) dst[i] = src[i];
        uint4 z; z.x = z.y = z.z = z.w = 0u;
        uint4* da = (uint4*)(smem + SO_A);
        for (int i = tid; i < 20480 / 16; i += GT) da[i] = z;
        if (tid < 16) sW[tid] = (tid < 12) ? Wh[tid] : bh[tid - 12];
    }
    __syncthreads();

    if (tid < RPC) {
        int seq = seq0 + tid;
        const float* hp = hist + (size_t)(seq >> 3) * (64 * 24) + (seq & 7);
        float a0v = hp[0], a1v = hp[8], a2v = hp[16];
        float xs[4];
#pragma unroll
        for (int o = 0; o < 4; o++)
            xs[o] = sigf(sW[o*3+0]*a0v + sW[o*3+1]*a1v + sW[o*3+2]*a2v + sW[12+o]);
        int mtile = tid >> 4, r = tid & 15;
        char* base = smem + SO_A + (size_t)((0 * 4 + mtile) * 5 + 4) * 512
                   + ((r & 7) * 4) * 16 + (r >> 3) * 4;
        *(uint32_t*)(base)      = h2bits(xs[0], xs[1]);
        *(uint32_t*)(base + 16) = h2bits(xs[2], xs[3]);
        *(uint32_t*)(base + 32) = h2bits(1.0f, 0.0f);
    }
    __syncthreads();

    const bool is_stager = (gtid < 32);
    const float* hbase = nullptr;
    if (is_stager) {
        int seq = seq0 + mg * 32 + gtid;
        hbase = hist + (size_t)(seq >> 3) * (64 * 24) + (seq & 7);
    }

    float hprev[2][2][2][2];   // [mt][rh][sb][jp]
#pragma unroll
    for (int a = 0; a < 2; a++)
#pragma unroll
        for (int b = 0; b < 2; b++)
#pragma unroll
            for (int c = 0; c < 2; c++) { hprev[a][b][c][0] = 0.f; hprev[a][b][c][1] = 0.f; }

#pragma unroll 1
    for (int t = 0; t < NT; t++) {
        const int buf = t & 1, bufn = buf ^ 1;
        const bool stage = is_stager && (t + 1 < NT);

        float xs[4];
        if (stage) {
            const float* hp = hbase + (size_t)(t + 1) * 24;
            float a0v = hp[0], a1v = hp[8], a2v = hp[16];
#pragma unroll
            for (int o = 0; o < 4; o++)
                xs[o] = sigf(sW[o*3+0]*a0v + sW[o*3+1]*a1v + sW[o*3+2]*a2v + sW[12+o]);
        }

        float acc[2][4][2][4];
#pragma unroll
        for (int mt = 0; mt < 2; mt++)
#pragma unroll
            for (int gt = 0; gt < 4; gt++)
#pragma unroll
                for (int sb = 0; sb < 2; sb++)
#pragma unroll
                    for (int r = 0; r < 4; r++) acc[mt][gt][sb][r] = 0.0f;

#pragma unroll
        for (int kt = 0; kt < 4; kt++) {
            uint4 a0 = *(const uint4*)(smem + SO_A + (size_t)(((buf*4) + mg*2 + 0)*5 + kt)*512 + l*16);
            uint4 a1 = *(const uint4*)(smem + SO_A + (size_t)(((buf*4) + mg*2 + 1)*5 + kt)*512 + l*16);
#pragma unroll
            for (int sb = 0; sb < 2; sb++) {
                uint4 b4 = *(const uint4*)(smem + SO_B4 + (size_t)(((ng*2+sb)*4 + kt))*512 + l*16);
                hmma(acc[0][2][sb], a0, b4.x, b4.y);
                hmma(acc[0][2][sb], a0, b4.z, b4.w);
                hmma(acc[1][2][sb], a1, b4.x, b4.y);
                hmma(acc[1][2][sb], a1, b4.z, b4.w);
#pragma unroll
                for (int gt = 0; gt < 2; gt++) {
                    uint2 b2 = *(const uint2*)(smem + SO_B2 + (size_t)(((gt*8 + ng*2+sb)*4 + kt))*256 + l*8);
                    hmma(acc[0][gt][sb], a0, b2.x, b2.y);
                    hmma(acc[1][gt][sb], a1, b2.x, b2.y);
                }
            }
        }
        {
            uint4 a0 = *(const uint4*)(smem + SO_A + (size_t)(((buf*4) + mg*2 + 0)*5 + 4)*512 + l*16);
            uint4 a1 = *(const uint4*)(smem + SO_A + (size_t)(((buf*4) + mg*2 + 1)*5 + 4)*512 + l*16);
#pragma unroll
            for (int sb = 0; sb < 2; sb++) {
#pragma unroll
                for (int gt = 0; gt < 2; gt++) {
                    uint2 b2 = *(const uint2*)(smem + SO_BK2 + (size_t)((gt*8 + ng*2+sb))*256 + l*8);
                    hmma(acc[0][gt][sb], a0, b2.x, b2.y);
                    hmma(acc[1][gt][sb], a1, b2.x, b2.y);
                }
#pragma unroll
                for (int gt = 2; gt < 4; gt++) {
                    uint4 b4 = *(const uint4*)(smem + SO_BK4 + (size_t)(((gt-2)*8 + ng*2+sb))*512 + l*16);
                    hmma(acc[0][gt][sb], a0, b4.x, b4.y);
                    hmma(acc[0][gt][sb], a0, b4.z, b4.w);
                    hmma(acc[1][gt][sb], a1, b4.x, b4.y);
                    hmma(acc[1][gt][sb], a1, b4.z, b4.w);
                }
            }
        }

#pragma unroll
        for (int mt = 0; mt < 2; mt++) {
            uint32_t hw[4];
#pragma unroll
            for (int sb = 0; sb < 2; sb++)
#pragma unroll
            for (int rh = 0; rh < 2; rh++) {
                const int rg = rh * 2;
                float r0 = siga(acc[mt][0][sb][rg]);
                float z0 = siga(acc[mt][1][sb][rg]);
                float c0 = tanha(fmaf(r0, acc[mt][2][sb][rg], acc[mt][3][sb][rg]));
                float h0 = fmaf(z0, hprev[mt][rh][sb][0] - c0, c0);
                float r1 = siga(acc[mt][0][sb][rg+1]);
                float z1 = siga(acc[mt][1][sb][rg+1]);
                float c1 = tanha(fmaf(r1, acc[mt][2][sb][rg+1], acc[mt][3][sb][rg+1]));
                float h1 = fmaf(z1, hprev[mt][rh][sb][1] - c1, c1);
                hprev[mt][rh][sb][0] = h0;
                hprev[mt][rh][sb][1] = h1;
                hw[rh + 2 * sb] = h2bits(h0, h1);

                if (t == NT - 1) {
                    const int m  = mg * 32 + mt * 16 + rh * 8 + lr;
                    const int j0 = ng * 16 + sb * 8 + 2 * c4;
                    float2 hv; hv.x = h0; hv.y = h1;
                    *(float2*)(&g_hidden[(size_t)(seq0 + m) * NH + j0]) = hv;
                }
            }
            uint4 v; v.x = hw[0]; v.y = hw[1]; v.z = hw[2]; v.w = hw[3];
            *(uint4*)(smem + SO_A + (size_t)(((bufn*4) + mg*2 + mt)*5 + ng)*512 + l*16) = v;
        }

        if (stage) {
            int m = mg * 32 + gtid;
            int mtile = m >> 4, r = m & 15;
            char* base = smem + SO_A + (size_t)((bufn * 4 + mtile) * 5 + 4) * 512
                       + ((r & 7) * 4) * 16 + (r >> 3) * 4;
            *(uint32_t*)(base)      = h2bits(xs[0], xs[1]);
            *(uint32_t*)(base + 16) = h2bits(xs[2], xs[3]);
            *(uint32_t*)(base + 32) = h2bits(1.0f, 0.0f);
        }
        asm volatile("bar.sync %0, 128;" :: "r"(1 + mg) : "memory");
    }
}

// ---------------------------------------------------------------------------
// Kernel 3: lane MLP + phase competition head. 4 batches per 256-thread block.
// This round: occupancy 3 blocks/SM + broken dependency chains.
// ---------------------------------------------------------------------------
__global__ void __launch_bounds__(256, 3)
post_kernel(const float* __restrict__ feat,
            const float* __restrict__ emb_phase,
            const float* __restrict__ Wv,  const float* __restrict__ bv,
            const float* __restrict__ Wl,  const float* __restrict__ bl,
            const float* __restrict__ Wcf, const float* __restrict__ bcf,
            const float* __restrict__ Wcm, const float* __restrict__ bcm,
            const float* __restrict__ Wfin,const float* __restrict__ bfin,
            float* __restrict__ out)
{
    __shared__ float s_hid[4][NL][NH];
    __shared__ float s_lf[4][NL][8];
    __shared__ float s_line[4][NL][16];
    __shared__ float s_pp[4][NL][16];
    __shared__ float s_Wl[16 * 72];
    __shared__ float s_yc[NL * 7 * 20];
    __shared__ float s_val[4][NL][7];

    const int tid = threadIdx.x;
    const int sub = tid >> 6;          // 0..3
    const int st  = tid & 63;
    const int b   = blockIdx.x * 4 + sub;

    for (int i = tid; i < 16 * 72; i += 256) s_Wl[i] = Wl[i];
    for (int i = tid; i < NL * 7 * 20; i += 256) s_yc[i] = g_yc[i];
    for (int i = st; i < NL * NH; i += 64)
        s_hid[sub][i >> 6][i & 63] = g_hidden[(size_t)b * (NL * NH) + i];

    {
        int l = st >> 3, f = st & 7;
        if (f < 4) {
            float vr = feat[b * 16 + 8 + l];
            s_lf[sub][l][f] = sigf(fmaf(vr, Wv[f], bv[f]));
        } else {
            int c = f - 4;
            int pid = (int)feat[b * 16 + l];
            s_lf[sub][l][f] = sigf(emb_phase[pid * 4 + c]);
        }
    }
    __syncthreads();

    // line = relu(lane_feat @ Wl^T + bl) — 4 independent partial sums
    for (int i = st; i < NL * 16; i += 64) {
        int l = i >> 4, o = i & 15;
        const float* wrow = &s_Wl[o * 72];
        const float* lf = &s_lf[sub][l][0];
        const float* hp = &s_hid[sub][l][0];
        float v0 = bl[o], v1 = 0.0f, v2 = 0.0f, v3 = 0.0f;
#pragma unroll
        for (int c = 0; c < 8; c += 4) {
            v0 = fmaf(lf[c],     wrow[c],     v0);
            v1 = fmaf(lf[c + 1], wrow[c + 1], v1);
            v2 = fmaf(lf[c + 2], wrow[c + 2], v2);
            v3 = fmaf(lf[c + 3], wrow[c + 3], v3);
        }
#pragma unroll
        for (int k = 0; k < NH; k += 4) {
            v0 = fmaf(hp[k],     wrow[8 + k],     v0);
            v1 = fmaf(hp[k + 1], wrow[8 + k + 1], v1);
            v2 = fmaf(hp[k + 2], wrow[8 + k + 2], v2);
            v3 = fmaf(hp[k + 3], wrow[8 + k + 3], v3);
        }
        s_line[sub][l][o] = fmaxf((v0 + v1) + (v2 + v3), 0.0f);
    }
    __syncthreads();

    for (int i = st; i < NL * 16; i += 64) {
        int p = i >> 4, o = i & 15;
        s_pp[sub][p][o] = s_line[sub][c_PL[p][0]][o] + s_line[sub][c_PL[p][1]][o];
    }
    __syncthreads();

    if (st < 56) {
        int p = st / 7, qi = st % 7;
        int jq = (qi < p) ? qi : qi + 1;

        float xf[20];
#pragma unroll
        for (int o = 0; o < 20; o++) {
            const float* wc = Wcf + o * 32;
            float v0 = bcf[o], v1 = 0.0f, v2 = 0.0f, v3 = 0.0f;
#pragma unroll
            for (int c = 0; c < 16; c += 4) {
                v0 = fmaf(s_pp[sub][p][c],     wc[c],     v0);
                v1 = fmaf(s_pp[sub][p][c + 1], wc[c + 1], v1);
                v2 = fmaf(s_pp[sub][p][c + 2], wc[c + 2], v2);
                v3 = fmaf(s_pp[sub][p][c + 3], wc[c + 3], v3);
            }
#pragma unroll
            for (int c = 0; c < 16; c += 4) {
                v0 = fmaf(s_pp[sub][jq][c],     wc[16 + c],     v0);
                v1 = fmaf(s_pp[sub][jq][c + 1], wc[16 + c + 1], v1);
                v2 = fmaf(s_pp[sub][jq][c + 2], wc[16 + c + 2], v2);
                v3 = fmaf(s_pp[sub][jq][c + 3], wc[16 + c + 3], v3);
            }
            xf[o] = fmaxf((v0 + v1) + (v2 + v3), 0.0f) * s_yc[(p * 7 + qi) * 20 + o];
        }
        float val = bfin[0];
#pragma unroll
        for (int o = 0; o < 20; o++) {
            const float* wm = Wcm + o * 20;
            float v0 = bcm[o], v1 = 0.0f;
#pragma unroll
            for (int c = 0; c < 20; c += 2) {
                v0 = fmaf(xf[c],     wm[c],     v0);
                v1 = fmaf(xf[c + 1], wm[c + 1], v1);
            }
            val = fmaf(fmaxf(v0 + v1, 0.0f), Wfin[o], val);
        }
        s_val[sub][p][qi] = val;
    }
    __syncthreads();

    if (st < NL) {
        float acc = 0.0f;
#pragma unroll
        for (int q = 0; q < 7; q++) acc += s_val[sub][st][q];
        out[b * NL + st] = acc;
    }
}

// ---------------------------------------------------------------------------
// Launch
// ---------------------------------------------------------------------------
extern "C" void kernel_launch(void* const* d_in, const int* in_sizes, int n_in,
                              void* d_out, int out_size)
{
    const float* feature  = (const float*)d_in[0];
    const float* history  = (const float*)d_in[1];
    const int*   relation = (const int*)  d_in[2];
    const float* emb_phase= (const float*)d_in[3];
    const float* Wv       = (const float*)d_in[4];
    const float* bv       = (const float*)d_in[5];
    const float* Wh       = (const float*)d_in[6];
    const float* bh       = (const float*)d_in[7];
    const float* Wih      = (const float*)d_in[8];
    const float* Whh      = (const float*)d_in[9];
    const float* bih      = (const float*)d_in[10];
    const float* bhh      = (const float*)d_in[11];
    const float* Wl       = (const float*)d_in[12];
    const float* bl       = (const float*)d_in[13];
    const float* emb_const= (const float*)d_in[14];
    const float* Wcf      = (const float*)d_in[15];
    const float* bcf      = (const float*)d_in[16];
    const float* Wcc      = (const float*)d_in[17];
    const float* bcc      = (const float*)d_in[18];
    const float* Wcm      = (const float*)d_in[19];
    const float* bcm      = (const float*)d_in[20];
    const float* Wfin     = (const float*)d_in[21];
    const float* bfin     = (const float*)d_in[22];
    float* out = (float*)d_out;

    cudaFuncSetAttribute(gru_kernel, cudaFuncAttributeMaxDynamicSharedMemorySize, SMEMSZ);

    build_tables<<<21, 256>>>(Wih, Whh, bih, bhh, relation, emb_const, Wcc, bcc);
    gru_kernel<<<GCTA, GT, SMEMSZ>>>(history, Wh, bh);
    post_kernel<<<NB / 4, 256>>>(feature, emb_phase, Wv, bv, Wl, bl,
                                 Wcf, bcf, Wcm, bcm, Wfin, bfin, out);
}

// round 14
// speedup vs baseline: 1.0649x; 1.0649x over previous
#include <cuda_runtime.h>
#include <cuda_fp16.h>
#include <stdint.h>
#include <math.h>

#define NB   2048
#define NT   64
#define NL   8
#define NH   64
#define NSEQ (NB*NL)          // 16384
#define RPC  64               // rows per GRU CTA
#define GCTA (NSEQ/RPC)       // 256 CTAs
#define GT   256              // GRU threads per CTA

// ---- SMEM map for GRU mainloop (bytes) -------------------------------------
// B2 : Whh r,z hi-only   : 64 tiles x 256B = 16384
// B4 : Whh ghn hi/lo     : 32 tiles x 512B = 16384
// BK2: kt4 r,z hi-only   : 16 tiles x 256B =  4096
// BK4: kt4 gin hi/lo     :  8 tiles x 512B =  4096   (ghn bias folded to epilogue)
#define SO_B2   0
#define SO_B4   16384
#define SO_BK2  32768
#define SO_BK4  36864
#define SO_A    40960
#define SMEMSZ  61440

// ---- scratch (__device__ globals; allocs forbidden) -----------------------
__device__ __align__(16) float g_hidden[NSEQ * NH];   // [seq][64]
__device__ __align__(16) char g_Ball[40960];          // packed B regions
__device__ __align__(16) float g_yc[NL * 7 * 20];     // relu(ce@Wcc^T+bcc)

__device__ __forceinline__ float sigf(float x) {
    return __fdividef(1.0f, 1.0f + __expf(-x));
}
__device__ __forceinline__ float tanha(float x) {
    float y;
    asm("tanh.approx.f32 %0, %1;" : "=f"(y) : "f"(x));
    return y;
}
__device__ __forceinline__ float siga(float x) {     // sigmoid via tanh, 1 MUFU
    return fmaf(0.5f, tanha(0.5f * x), 0.5f);
}
__device__ __forceinline__ uint32_t h2bits(float a, float b) {
    __half2 h = __floats2half2_rn(a, b);
    return *reinterpret_cast<uint32_t*>(&h);
}

// mma.sync m16n8k16 f16 -> f32 accumulate
__device__ __forceinline__ void hmma(float c[4], const uint4& a,
                                     uint32_t b0, uint32_t b1) {
    asm("mma.sync.aligned.m16n8k16.row.col.f32.f16.f16.f32 "
        "{%0,%1,%2,%3},{%4,%5,%6,%7},{%8,%9},{%0,%1,%2,%3};"
        : "+f"(c[0]), "+f"(c[1]), "+f"(c[2]), "+f"(c[3])
        : "r"(a.x), "r"(a.y), "r"(a.z), "r"(a.w), "r"(b0), "r"(b1));
}

__constant__ int c_PL[8][2] = {{1,3},{0,2},{5,7},{4,6},{0,1},{2,3},{4,5},{6,7}};

// ---------------------------------------------------------------------------
// Kernel 0: pack weights + yc table, one launch.
// gates g: 0=r, 1=z, 2=ghn, 3=gin
// ---------------------------------------------------------------------------
__device__ __forceinline__ float b4val(int g, int nl, int k,
                                       const float* Wih, const float* bih,
                                       const float* bhh) {
    if (k < 4) {
        if (g == 0) return Wih[nl * 4 + k];
        if (g == 1) return Wih[(64 + nl) * 4 + k];
        return Wih[(128 + nl) * 4 + k];           // g==3 (gin)
    }
    if (k == 4) {
        if (g == 0) return bih[nl] + bhh[nl];
        if (g == 1) return bih[64 + nl] + bhh[64 + nl];
        return bih[128 + nl];                     // g==3 (gin)
    }
    return 0.0f;
}

__global__ void build_tables(const float* __restrict__ Wih, const float* __restrict__ Whh,
                             const float* __restrict__ bih, const float* __restrict__ bhh,
                             const int* __restrict__ relation,
                             const float* __restrict__ emb_const,
                             const float* __restrict__ Wcc,
                             const float* __restrict__ bcc)
{
    int i = blockIdx.x * blockDim.x + threadIdx.x;
    if (i >= 4096) {
        int j = i - 4096;
        if (j < NL * 7 * 20) {
            int o = j % 20, pq = j / 20;
            int p = pq / 7, q = pq % 7;
            const float* ce = emb_const + relation[p * 7 + q] * 4;
            float v = bcc[o];
#pragma unroll
            for (int c = 0; c < 4; c++) v = fmaf(ce[c], Wcc[o * 4 + c], v);
            g_yc[j] = fmaxf(v, 0.0f);
        }
        return;
    }
    if (i >= 3840) return;   // gap: BK4 shrank to 8 tiles
    int lane = i & 31;
    float w[4];
    char* dst;
    bool wide;

    if (i < 2048) {                       // B2: Whh r,z hi-only
        int tile = i >> 5;
        int kt = tile & 3, nt16 = tile >> 2;
        int g = nt16 >> 3, nb = nt16 & 7;
        int row = g * 64 + nb * 8 + (lane >> 2);
        int k0 = kt * 16 + 2 * (lane & 3);
        w[0] = Whh[row*64 + k0];     w[1] = Whh[row*64 + k0 + 1];
        w[2] = Whh[row*64 + k0 + 8]; w[3] = Whh[row*64 + k0 + 9];
        dst = g_Ball + SO_B2 + tile * 256 + lane * 8;  wide = false;
    } else if (i < 3072) {                // B4: Whh ghn hi/lo
        int idx = i - 2048, tile = idx >> 5;
        int kt = tile & 3, nt8 = tile >> 2;
        int row = 128 + nt8 * 8 + (lane >> 2);
        int k0 = kt * 16 + 2 * (lane & 3);
        w[0] = Whh[row*64 + k0];     w[1] = Whh[row*64 + k0 + 1];
        w[2] = Whh[row*64 + k0 + 8]; w[3] = Whh[row*64 + k0 + 9];
        dst = g_Ball + SO_B4 + tile * 512 + lane * 16; wide = true;
    } else if (i < 3584) {                // BK2: kt4 r,z hi-only
        int idx = i - 3072, tile = idx >> 5;
        int g = tile >> 3, nb = tile & 7;
        int nl = nb * 8 + (lane >> 2);
        int k0 = 2 * (lane & 3);
        w[0] = b4val(g, nl, k0,     Wih, bih, bhh);
        w[1] = b4val(g, nl, k0 + 1, Wih, bih, bhh);
        w[2] = b4val(g, nl, k0 + 8, Wih, bih, bhh);
        w[3] = b4val(g, nl, k0 + 9, Wih, bih, bhh);
        dst = g_Ball + SO_BK2 + tile * 256 + lane * 8; wide = false;
    } else {                              // BK4: kt4 gin hi/lo (8 tiles)
        int idx = i - 3584, tile = idx >> 5;   // 0..7 = nb
        int nl = tile * 8 + (lane >> 2);
        int k0 = 2 * (lane & 3);
        w[0] = b4val(3, nl, k0,     Wih, bih, bhh);
        w[1] = b4val(3, nl, k0 + 1, Wih, bih, bhh);
        w[2] = b4val(3, nl, k0 + 8, Wih, bih, bhh);
        w[3] = b4val(3, nl, k0 + 9, Wih, bih, bhh);
        dst = g_Ball + SO_BK4 + tile * 512 + lane * 16; wide = true;
    }

    __half hi[4], lo[4];
#pragma unroll
    for (int q = 0; q < 4; q++) {
        hi[q] = __float2half_rn(w[q]);
        lo[q] = __float2half_rn(w[q] - __half2float(hi[q]));
    }
    uint2 vh;
    { __half2 p(hi[0], hi[1]); vh.x = *reinterpret_cast<uint32_t*>(&p); }
    { __half2 p(hi[2], hi[3]); vh.y = *reinterpret_cast<uint32_t*>(&p); }
    *(uint2*)dst = vh;
    if (wide) {
        uint2 vl;
        { __half2 p(lo[0], lo[1]); vl.x = *reinterpret_cast<uint32_t*>(&p); }
        { __half2 p(lo[2], lo[3]); vl.y = *reinterpret_cast<uint32_t*>(&p); }
        *(uint2*)(dst + 8) = vl;
    }
}

// ---------------------------------------------------------------------------
// Kernel 2: tensor-core GRU. ghn bias applied in fp32 epilogue.
// ---------------------------------------------------------------------------
__global__ void __launch_bounds__(GT, 2)
gru_kernel(const float* __restrict__ hist,
           const float* __restrict__ Wh,
           const float* __restrict__ bh,
           const float* __restrict__ bhh)
{
    extern __shared__ char smem[];
    __shared__ float sW[16];   // [0..11]=Wh, [12..15]=bh
    const int tid = threadIdx.x;
    const int l   = tid & 31;
    const int wid = tid >> 5;
    const int mg  = wid >> 2;
    const int ng  = wid & 3;
    const int gtid = tid & 127;
    const int c4  = l & 3;
    const int lr  = l >> 2;
    const int seq0 = blockIdx.x * RPC;

    {
        const uint4* src = (const uint4*)g_Ball;
        uint4* dst = (uint4*)smem;
        for (int i = tid; i < 40960 / 16; i += GT) dst[i] = src[i];
        uint4 z; z.x = z.y = z.z = z.w = 0u;
        uint4* da = (uint4*)(smem + SO_A);
        for (int i = tid; i < 20480 / 16; i += GT) da[i] = z;
        if (tid < 16) sW[tid] = (tid < 12) ? Wh[tid] : bh[tid - 12];
    }

    // ghn bias constants for this thread's 4 j's: j = ng*16 + sb*8 + 2*c4 + jp
    float bhn[2][2];
#pragma unroll
    for (int sb = 0; sb < 2; sb++)
#pragma unroll
    for (int jp = 0; jp < 2; jp++)
        bhn[sb][jp] = bhh[128 + ng * 16 + sb * 8 + 2 * c4 + jp];

    __syncthreads();

    if (tid < RPC) {
        int seq = seq0 + tid;
        const float* hp = hist + (size_t)(seq >> 3) * (64 * 24) + (seq & 7);
        float a0v = hp[0], a1v = hp[8], a2v = hp[16];
        float xs[4];
#pragma unroll
        for (int o = 0; o < 4; o++)
            xs[o] = sigf(sW[o*3+0]*a0v + sW[o*3+1]*a1v + sW[o*3+2]*a2v + sW[12+o]);
        int mtile = tid >> 4, r = tid & 15;
        char* base = smem + SO_A + (size_t)((0 * 4 + mtile) * 5 + 4) * 512
                   + ((r & 7) * 4) * 16 + (r >> 3) * 4;
        *(uint32_t*)(base)      = h2bits(xs[0], xs[1]);
        *(uint32_t*)(base + 16) = h2bits(xs[2], xs[3]);
        *(uint32_t*)(base + 32) = h2bits(1.0f, 0.0f);
    }
    __syncthreads();

    const bool is_stager = (gtid < 32);
    const float* hbase = nullptr;
    if (is_stager) {
        int seq = seq0 + mg * 32 + gtid;
        hbase = hist + (size_t)(seq >> 3) * (64 * 24) + (seq & 7);
    }

    float hprev[2][2][2][2];   // [mt][rh][sb][jp]
#pragma unroll
    for (int a = 0; a < 2; a++)
#pragma unroll
        for (int b = 0; b < 2; b++)
#pragma unroll
            for (int c = 0; c < 2; c++) { hprev[a][b][c][0] = 0.f; hprev[a][b][c][1] = 0.f; }

#pragma unroll 1
    for (int t = 0; t < NT; t++) {
        const int buf = t & 1, bufn = buf ^ 1;
        const bool stage = is_stager && (t + 1 < NT);

        float xs[4];
        if (stage) {
            const float* hp = hbase + (size_t)(t + 1) * 24;
            float a0v = hp[0], a1v = hp[8], a2v = hp[16];
#pragma unroll
            for (int o = 0; o < 4; o++)
                xs[o] = sigf(sW[o*3+0]*a0v + sW[o*3+1]*a1v + sW[o*3+2]*a2v + sW[12+o]);
        }

        float acc[2][4][2][4];
#pragma unroll
        for (int mt = 0; mt < 2; mt++)
#pragma unroll
            for (int gt = 0; gt < 4; gt++)
#pragma unroll
                for (int sb = 0; sb < 2; sb++)
#pragma unroll
                    for (int r = 0; r < 4; r++) acc[mt][gt][sb][r] = 0.0f;

        // ---- HMMA mainloop: kt0-3 (h x Whh) --------------------------------
#pragma unroll
        for (int kt = 0; kt < 4; kt++) {
            uint4 a0 = *(const uint4*)(smem + SO_A + (size_t)(((buf*4) + mg*2 + 0)*5 + kt)*512 + l*16);
            uint4 a1 = *(const uint4*)(smem + SO_A + (size_t)(((buf*4) + mg*2 + 1)*5 + kt)*512 + l*16);
#pragma unroll
            for (int sb = 0; sb < 2; sb++) {
                uint4 b4 = *(const uint4*)(smem + SO_B4 + (size_t)(((ng*2+sb)*4 + kt))*512 + l*16);
                hmma(acc[0][2][sb], a0, b4.x, b4.y);
                hmma(acc[0][2][sb], a0, b4.z, b4.w);
                hmma(acc[1][2][sb], a1, b4.x, b4.y);
                hmma(acc[1][2][sb], a1, b4.z, b4.w);
#pragma unroll
                for (int gt = 0; gt < 2; gt++) {
                    uint2 b2 = *(const uint2*)(smem + SO_B2 + (size_t)(((gt*8 + ng*2+sb)*4 + kt))*256 + l*8);
                    hmma(acc[0][gt][sb], a0, b2.x, b2.y);
                    hmma(acc[1][gt][sb], a1, b2.x, b2.y);
                }
            }
        }
        // ---- kt4: x,bias (r,z hi-only; gin hi/lo; NO ghn tile) -------------
        {
            uint4 a0 = *(const uint4*)(smem + SO_A + (size_t)(((buf*4) + mg*2 + 0)*5 + 4)*512 + l*16);
            uint4 a1 = *(const uint4*)(smem + SO_A + (size_t)(((buf*4) + mg*2 + 1)*5 + 4)*512 + l*16);
#pragma unroll
            for (int sb = 0; sb < 2; sb++) {
#pragma unroll
                for (int gt = 0; gt < 2; gt++) {
                    uint2 b2 = *(const uint2*)(smem + SO_BK2 + (size_t)((gt*8 + ng*2+sb))*256 + l*8);
                    hmma(acc[0][gt][sb], a0, b2.x, b2.y);
                    hmma(acc[1][gt][sb], a1, b2.x, b2.y);
                }
                uint4 b4 = *(const uint4*)(smem + SO_BK4 + (size_t)((ng*2+sb))*512 + l*16);
                hmma(acc[0][3][sb], a0, b4.x, b4.y);
                hmma(acc[0][3][sb], a0, b4.z, b4.w);
                hmma(acc[1][3][sb], a1, b4.x, b4.y);
                hmma(acc[1][3][sb], a1, b4.z, b4.w);
            }
        }

        // ---- epilogue: gate math + fp16 h STS.128 per mt --------------------
#pragma unroll
        for (int mt = 0; mt < 2; mt++) {
            uint32_t hw[4];
#pragma unroll
            for (int sb = 0; sb < 2; sb++)
#pragma unroll
            for (int rh = 0; rh < 2; rh++) {
                const int rg = rh * 2;
                float r0 = siga(acc[mt][0][sb][rg]);
                float z0 = siga(acc[mt][1][sb][rg]);
                float c0 = tanha(fmaf(r0, acc[mt][2][sb][rg] + bhn[sb][0], acc[mt][3][sb][rg]));
                float h0 = fmaf(z0, hprev[mt][rh][sb][0] - c0, c0);
                float r1 = siga(acc[mt][0][sb][rg+1]);
                float z1 = siga(acc[mt][1][sb][rg+1]);
                float c1 = tanha(fmaf(r1, acc[mt][2][sb][rg+1] + bhn[sb][1], acc[mt][3][sb][rg+1]));
                float h1 = fmaf(z1, hprev[mt][rh][sb][1] - c1, c1);
                hprev[mt][rh][sb][0] = h0;
                hprev[mt][rh][sb][1] = h1;
                hw[rh + 2 * sb] = h2bits(h0, h1);

                if (t == NT - 1) {
                    const int m  = mg * 32 + mt * 16 + rh * 8 + lr;
                    const int j0 = ng * 16 + sb * 8 + 2 * c4;
                    float2 hv; hv.x = h0; hv.y = h1;
                    *(float2*)(&g_hidden[(size_t)(seq0 + m) * NH + j0]) = hv;
                }
            }
            uint4 v; v.x = hw[0]; v.y = hw[1]; v.z = hw[2]; v.w = hw[3];
            *(uint4*)(smem + SO_A + (size_t)(((bufn*4) + mg*2 + mt)*5 + ng)*512 + l*16) = v;
        }

        if (stage) {
            int m = mg * 32 + gtid;
            int mtile = m >> 4, r = m & 15;
            char* base = smem + SO_A + (size_t)((bufn * 4 + mtile) * 5 + 4) * 512
                       + ((r & 7) * 4) * 16 + (r >> 3) * 4;
            *(uint32_t*)(base)      = h2bits(xs[0], xs[1]);
            *(uint32_t*)(base + 16) = h2bits(xs[2], xs[3]);
            *(uint32_t*)(base + 32) = h2bits(1.0f, 0.0f);
        }
        asm volatile("bar.sync %0, 128;" :: "r"(1 + mg) : "memory");
    }
}

// ---------------------------------------------------------------------------
// Kernel 3: lane MLP + phase competition head (R12's proven version).
// ---------------------------------------------------------------------------
__global__ void __launch_bounds__(256)
post_kernel(const float* __restrict__ feat,
            const float* __restrict__ emb_phase,
            const float* __restrict__ Wv,  const float* __restrict__ bv,
            const float* __restrict__ Wl,  const float* __restrict__ bl,
            const float* __restrict__ Wcf, const float* __restrict__ bcf,
            const float* __restrict__ Wcm, const float* __restrict__ bcm,
            const float* __restrict__ Wfin,const float* __restrict__ bfin,
            float* __restrict__ out)
{
    __shared__ float s_hid[4][NL][NH];
    __shared__ float s_lf[4][NL][8];
    __shared__ float s_line[4][NL][16];
    __shared__ float s_pp[4][NL][16];
    __shared__ float s_Wl[16 * 72];
    __shared__ float s_yc[NL * 7 * 20];
    __shared__ float s_val[4][NL][7];

    const int tid = threadIdx.x;
    const int sub = tid >> 6;          // 0..3
    const int st  = tid & 63;
    const int b   = blockIdx.x * 4 + sub;

    for (int i = tid; i < 16 * 72; i += 256) s_Wl[i] = Wl[i];
    for (int i = tid; i < NL * 7 * 20; i += 256) s_yc[i] = g_yc[i];
    for (int i = st; i < NL * NH; i += 64)
        s_hid[sub][i >> 6][i & 63] = g_hidden[(size_t)b * (NL * NH) + i];

    {
        int l = st >> 3, f = st & 7;
        if (f < 4) {
            float vr = feat[b * 16 + 8 + l];
            s_lf[sub][l][f] = sigf(fmaf(vr, Wv[f], bv[f]));
        } else {
            int c = f - 4;
            int pid = (int)feat[b * 16 + l];
            s_lf[sub][l][f] = sigf(emb_phase[pid * 4 + c]);
        }
    }
    __syncthreads();

    for (int i = st; i < NL * 16; i += 64) {
        int l = i >> 4, o = i & 15;
        const float* wrow = &s_Wl[o * 72];
        float v = bl[o];
#pragma unroll
        for (int c = 0; c < 8; c++)  v = fmaf(s_lf[sub][l][c], wrow[c], v);
#pragma unroll
        for (int k = 0; k < NH; k++) v = fmaf(s_hid[sub][l][k], wrow[8 + k], v);
        s_line[sub][l][o] = fmaxf(v, 0.0f);
    }
    __syncthreads();

    for (int i = st; i < NL * 16; i += 64) {
        int p = i >> 4, o = i & 15;
        s_pp[sub][p][o] = s_line[sub][c_PL[p][0]][o] + s_line[sub][c_PL[p][1]][o];
    }
    __syncthreads();

    if (st < 56) {
        int p = st / 7, qi = st % 7;
        int jq = (qi < p) ? qi : qi + 1;

        float xf[20];
#pragma unroll
        for (int o = 0; o < 20; o++) {
            const float* wc = Wcf + o * 32;
            float v = bcf[o];
#pragma unroll
            for (int c = 0; c < 16; c++) v = fmaf(s_pp[sub][p][c],  wc[c],      v);
#pragma unroll
            for (int c = 0; c < 16; c++) v = fmaf(s_pp[sub][jq][c], wc[16 + c], v);
            xf[o] = fmaxf(v, 0.0f) * s_yc[(p * 7 + qi) * 20 + o];
        }
        float val = bfin[0];
#pragma unroll
        for (int o = 0; o < 20; o++) {
            const float* wm = Wcm + o * 20;
            float v = bcm[o];
#pragma unroll
            for (int c = 0; c < 20; c++) v = fmaf(xf[c], wm[c], v);
            val = fmaf(fmaxf(v, 0.0f), Wfin[o], val);
        }
        s_val[sub][p][qi] = val;
    }
    __syncthreads();

    if (st < NL) {
        float acc = 0.0f;
#pragma unroll
        for (int q = 0; q < 7; q++) acc += s_val[sub][st][q];
        out[b * NL + st] = acc;
    }
}

// ---------------------------------------------------------------------------
// Launch
// ---------------------------------------------------------------------------
extern "C" void kernel_launch(void* const* d_in, const int* in_sizes, int n_in,
                              void* d_out, int out_size)
{
    const float* feature  = (const float*)d_in[0];
    const float* history  = (const float*)d_in[1];
    const int*   relation = (const int*)  d_in[2];
    const float* emb_phase= (const float*)d_in[3];
    const float* Wv       = (const float*)d_in[4];
    const float* bv       = (const float*)d_in[5];
    const float* Wh       = (const float*)d_in[6];
    const float* bh       = (const float*)d_in[7];
    const float* Wih      = (const float*)d_in[8];
    const float* Whh      = (const float*)d_in[9];
    const float* bih      = (const float*)d_in[10];
    const float* bhh      = (const float*)d_in[11];
    const float* Wl       = (const float*)d_in[12];
    const float* bl       = (const float*)d_in[13];
    const float* emb_const= (const float*)d_in[14];
    const float* Wcf      = (const float*)d_in[15];
    const float* bcf      = (const float*)d_in[16];
    const float* Wcc      = (const float*)d_in[17];
    const float* bcc      = (const float*)d_in[18];
    const float* Wcm      = (const float*)d_in[19];
    const float* bcm      = (const float*)d_in[20];
    const float* Wfin     = (const float*)d_in[21];
    const float* bfin     = (const float*)d_in[22];
    float* out = (float*)d_out;

    cudaFuncSetAttribute(gru_kernel, cudaFuncAttributeMaxDynamicSharedMemorySize, SMEMSZ);

    build_tables<<<21, 256>>>(Wih, Whh, bih, bhh, relation, emb_const, Wcc, bcc);
    gru_kernel<<<GCTA, GT, SMEMSZ>>>(history, Wh, bh, bhh);
    post_kernel<<<NB / 4, 256>>>(feature, emb_phase, Wv, bv, Wl, bl,
                                 Wcf, bcf, Wcm, bcm, Wfin, bfin, out);
}

// round 15
// speedup vs baseline: 1.0841x; 1.0180x over previous
#include <cuda_runtime.h>
#include <cuda_fp16.h>
#include <stdint.h>
#include <math.h>

#define NB   2048
#define NT   64
#define NL   8
#define NH   64
#define NSEQ (NB*NL)          // 16384
#define RPC  64               // rows per GRU CTA
#define GCTA (NSEQ/RPC)       // 256 CTAs
#define GT   256              // GRU threads per CTA

// ---- SMEM map for GRU mainloop (bytes) -------------------------------------
// B2RZ : Whh r+z hi interleaved : 32 tiles x 512B = 16384
// B4   : Whh ghn hi/lo          : 32 tiles x 512B = 16384
// BK2RZ: kt4 r+z hi (k8)        :  8 tiles x 256B =  2048
// BK4  : kt4 gin hi/lo (k8)     :  8 tiles x 256B =  2048
#define SO_B2RZ  0
#define SO_B4    16384
#define SO_BK2RZ 32768
#define SO_BK4   34816
#define SO_A     36864
#define SMEMSZ   57344

// ---- scratch (__device__ globals; allocs forbidden) -----------------------
__device__ __align__(16) float g_hidden[NSEQ * NH];   // [seq][64]
__device__ __align__(16) char g_Ball[36864];          // packed B regions
__device__ __align__(16) float g_yc[NL * 7 * 20];     // relu(ce@Wcc^T+bcc)

__device__ __forceinline__ float sigf(float x) {
    return __fdividef(1.0f, 1.0f + __expf(-x));
}
__device__ __forceinline__ float tanha(float x) {
    float y;
    asm("tanh.approx.f32 %0, %1;" : "=f"(y) : "f"(x));
    return y;
}
__device__ __forceinline__ float siga(float x) {     // sigmoid via tanh, 1 MUFU
    return fmaf(0.5f, tanha(0.5f * x), 0.5f);
}
__device__ __forceinline__ uint32_t h2bits(float a, float b) {
    __half2 h = __floats2half2_rn(a, b);
    return *reinterpret_cast<uint32_t*>(&h);
}
__device__ __forceinline__ uint32_t packhi(float a, float b) {
    __half2 p(__float2half_rn(a), __float2half_rn(b));
    return *reinterpret_cast<uint32_t*>(&p);
}

// mma.sync m16n8k16 f16 -> f32 accumulate
__device__ __forceinline__ void hmma(float c[4], const uint4& a,
                                     uint32_t b0, uint32_t b1) {
    asm("mma.sync.aligned.m16n8k16.row.col.f32.f16.f16.f32 "
        "{%0,%1,%2,%3},{%4,%5,%6,%7},{%8,%9},{%0,%1,%2,%3};"
        : "+f"(c[0]), "+f"(c[1]), "+f"(c[2]), "+f"(c[3])
        : "r"(a.x), "r"(a.y), "r"(a.z), "r"(a.w), "r"(b0), "r"(b1));
}
// mma.sync m16n8k8 f16 -> f32 accumulate (kt4: only k0..7 nonzero)
__device__ __forceinline__ void hmma8(float c[4], uint32_t a0, uint32_t a1,
                                      uint32_t b0) {
    asm("mma.sync.aligned.m16n8k8.row.col.f32.f16.f16.f32 "
        "{%0,%1,%2,%3},{%4,%5},{%6},{%0,%1,%2,%3};"
        : "+f"(c[0]), "+f"(c[1]), "+f"(c[2]), "+f"(c[3])
        : "r"(a0), "r"(a1), "r"(b0));
}

__constant__ int c_PL[8][2] = {{1,3},{0,2},{5,7},{4,6},{0,1},{2,3},{4,5},{6,7}};

// ---------------------------------------------------------------------------
// Kernel 0: pack weights + yc table, one launch.
// gates g: 0=r, 1=z, 2=ghn, 3=gin
// ---------------------------------------------------------------------------
__device__ __forceinline__ float b4val(int g, int nl, int k,
                                       const float* Wih, const float* bih,
                                       const float* bhh) {
    if (k < 4) {
        if (g == 0) return Wih[nl * 4 + k];
        if (g == 1) return Wih[(64 + nl) * 4 + k];
        return Wih[(128 + nl) * 4 + k];           // g==3 (gin)
    }
    if (k == 4) {
        if (g == 0) return bih[nl] + bhh[nl];
        if (g == 1) return bih[64 + nl] + bhh[64 + nl];
        return bih[128 + nl];                     // g==3 (gin)
    }
    return 0.0f;
}

__global__ void build_tables(const float* __restrict__ Wih, const float* __restrict__ Whh,
                             const float* __restrict__ bih, const float* __restrict__ bhh,
                             const int* __restrict__ relation,
                             const float* __restrict__ emb_const,
                             const float* __restrict__ Wcc,
                             const float* __restrict__ bcc)
{
    int i = blockIdx.x * blockDim.x + threadIdx.x;
    if (i >= 4096) {
        int j = i - 4096;
        if (j < NL * 7 * 20) {
            int o = j % 20, pq = j / 20;
            int p = pq / 7, q = pq % 7;
            const float* ce = emb_const + relation[p * 7 + q] * 4;
            float v = bcc[o];
#pragma unroll
            for (int c = 0; c < 4; c++) v = fmaf(ce[c], Wcc[o * 4 + c], v);
            g_yc[j] = fmaxf(v, 0.0f);
        }
        return;
    }
    if (i >= 2560) return;
    int lane = i & 31;
    int lr = lane >> 2, c4 = lane & 3;

    if (i < 1024) {
        // B2RZ: tile (nb, kt), lane uint4 {r.b0, r.b1, z.b0, z.b1} (hi only)
        int tile = i >> 5;
        int kt = tile & 3, nb = tile >> 2;
        int row_r = nb * 8 + lr;
        int row_z = 64 + nb * 8 + lr;
        int k0 = kt * 16 + 2 * c4;
        uint4 v;
        v.x = packhi(Whh[row_r*64 + k0],     Whh[row_r*64 + k0 + 1]);
        v.y = packhi(Whh[row_r*64 + k0 + 8], Whh[row_r*64 + k0 + 9]);
        v.z = packhi(Whh[row_z*64 + k0],     Whh[row_z*64 + k0 + 1]);
        v.w = packhi(Whh[row_z*64 + k0 + 8], Whh[row_z*64 + k0 + 9]);
        *(uint4*)(g_Ball + SO_B2RZ + tile * 512 + lane * 16) = v;
    } else if (i < 2048) {
        // B4: Whh ghn hi/lo, tile (nb, kt), lane uint4 {hi.b0, hi.b1, lo.b0, lo.b1}
        int idx = i - 1024, tile = idx >> 5;
        int kt = tile & 3, nb = tile >> 2;
        int row = 128 + nb * 8 + lr;
        int k0 = kt * 16 + 2 * c4;
        float w[4] = { Whh[row*64 + k0],     Whh[row*64 + k0 + 1],
                       Whh[row*64 + k0 + 8], Whh[row*64 + k0 + 9] };
        __half hi[4];
#pragma unroll
        for (int q = 0; q < 4; q++) hi[q] = __float2half_rn(w[q]);
        uint4 v;
        { __half2 p(hi[0], hi[1]); v.x = *reinterpret_cast<uint32_t*>(&p); }
        { __half2 p(hi[2], hi[3]); v.y = *reinterpret_cast<uint32_t*>(&p); }
        v.z = packhi(w[0] - __half2float(hi[0]), w[1] - __half2float(hi[1]));
        v.w = packhi(w[2] - __half2float(hi[2]), w[3] - __half2float(hi[3]));
        *(uint4*)(g_Ball + SO_B4 + tile * 512 + lane * 16) = v;
    } else if (i < 2304) {
        // BK2RZ: tile nb, lane uint2 {r.b0k8, z.b0k8}  (k0 = 2*c4, only k<5 nonzero)
        int tile = (i - 2048) >> 5;
        int nl = tile * 8 + lr;
        int k0 = 2 * c4;
        uint2 v;
        v.x = packhi(b4val(0, nl, k0, Wih, bih, bhh), b4val(0, nl, k0 + 1, Wih, bih, bhh));
        v.y = packhi(b4val(1, nl, k0, Wih, bih, bhh), b4val(1, nl, k0 + 1, Wih, bih, bhh));
        *(uint2*)(g_Ball + SO_BK2RZ + tile * 256 + lane * 8) = v;
    } else {
        // BK4: tile nb, lane uint2 {gin_hi.b0k8, gin_lo.b0k8}
        int tile = (i - 2304) >> 5;
        int nl = tile * 8 + lr;
        int k0 = 2 * c4;
        float w0 = b4val(3, nl, k0,     Wih, bih, bhh);
        float w1 = b4val(3, nl, k0 + 1, Wih, bih, bhh);
        __half h0 = __float2half_rn(w0), h1 = __float2half_rn(w1);
        uint2 v;
        { __half2 p(h0, h1); v.x = *reinterpret_cast<uint32_t*>(&p); }
        v.y = packhi(w0 - __half2float(h0), w1 - __half2float(h1));
        *(uint2*)(g_Ball + SO_BK4 + tile * 256 + lane * 8) = v;
    }
}

// ---------------------------------------------------------------------------
// Kernel 2: tensor-core GRU. kt4 via m16n8k8; r,z B-frags paired; bhn folded.
// ---------------------------------------------------------------------------
__global__ void __launch_bounds__(GT, 2)
gru_kernel(const float* __restrict__ hist,
           const float* __restrict__ Wh,
           const float* __restrict__ bh,
           const float* __restrict__ bhh)
{
    extern __shared__ char smem[];
    __shared__ float sW[16];   // [0..11]=Wh, [12..15]=bh
    const int tid = threadIdx.x;
    const int l   = tid & 31;
    const int wid = tid >> 5;
    const int mg  = wid >> 2;
    const int ng  = wid & 3;
    const int gtid = tid & 127;
    const int c4  = l & 3;
    const int lr  = l >> 2;
    const int seq0 = blockIdx.x * RPC;

    {
        const uint4* src = (const uint4*)g_Ball;
        uint4* dst = (uint4*)smem;
        for (int i = tid; i < 36864 / 16; i += GT) dst[i] = src[i];
        uint4 z; z.x = z.y = z.z = z.w = 0u;
        uint4* da = (uint4*)(smem + SO_A);
        for (int i = tid; i < 20480 / 16; i += GT) da[i] = z;
        if (tid < 16) sW[tid] = (tid < 12) ? Wh[tid] : bh[tid - 12];
    }

    // ghn bias constants for this thread's 4 j's: j = ng*16 + sb*8 + 2*c4 + jp
    float bhn[2][2];
#pragma unroll
    for (int sb = 0; sb < 2; sb++)
#pragma unroll
    for (int jp = 0; jp < 2; jp++)
        bhn[sb][jp] = bhh[128 + ng * 16 + sb * 8 + 2 * c4 + jp];

    __syncthreads();

    if (tid < RPC) {
        int seq = seq0 + tid;
        const float* hp = hist + (size_t)(seq >> 3) * (64 * 24) + (seq & 7);
        float a0v = hp[0], a1v = hp[8], a2v = hp[16];
        float xs[4];
#pragma unroll
        for (int o = 0; o < 4; o++)
            xs[o] = sigf(sW[o*3+0]*a0v + sW[o*3+1]*a1v + sW[o*3+2]*a2v + sW[12+o]);
        int mtile = tid >> 4, r = tid & 15;
        char* base = smem + SO_A + (size_t)((0 * 4 + mtile) * 5 + 4) * 512
                   + ((r & 7) * 4) * 16 + (r >> 3) * 4;
        *(uint32_t*)(base)      = h2bits(xs[0], xs[1]);
        *(uint32_t*)(base + 16) = h2bits(xs[2], xs[3]);
        *(uint32_t*)(base + 32) = h2bits(1.0f, 0.0f);
    }
    __syncthreads();

    const bool is_stager = (gtid < 32);
    const float* hbase = nullptr;
    if (is_stager) {
        int seq = seq0 + mg * 32 + gtid;
        hbase = hist + (size_t)(seq >> 3) * (64 * 24) + (seq & 7);
    }

    float hprev[2][2][2][2];   // [mt][rh][sb][jp]
#pragma unroll
    for (int a = 0; a < 2; a++)
#pragma unroll
        for (int b = 0; b < 2; b++)
#pragma unroll
            for (int c = 0; c < 2; c++) { hprev[a][b][c][0] = 0.f; hprev[a][b][c][1] = 0.f; }

#pragma unroll 1
    for (int t = 0; t < NT; t++) {
        const int buf = t & 1, bufn = buf ^ 1;
        const bool stage = is_stager && (t + 1 < NT);

        float xs[4];
        if (stage) {
            const float* hp = hbase + (size_t)(t + 1) * 24;
            float a0v = hp[0], a1v = hp[8], a2v = hp[16];
#pragma unroll
            for (int o = 0; o < 4; o++)
                xs[o] = sigf(sW[o*3+0]*a0v + sW[o*3+1]*a1v + sW[o*3+2]*a2v + sW[12+o]);
        }

        float acc[2][4][2][4];
#pragma unroll
        for (int mt = 0; mt < 2; mt++)
#pragma unroll
            for (int gt = 0; gt < 4; gt++)
#pragma unroll
                for (int sb = 0; sb < 2; sb++)
#pragma unroll
                    for (int r = 0; r < 4; r++) acc[mt][gt][sb][r] = 0.0f;

        // ---- HMMA mainloop: kt0-3 (h x Whh) --------------------------------
#pragma unroll
        for (int kt = 0; kt < 4; kt++) {
            uint4 a0 = *(const uint4*)(smem + SO_A + (size_t)(((buf*4) + mg*2 + 0)*5 + kt)*512 + l*16);
            uint4 a1 = *(const uint4*)(smem + SO_A + (size_t)(((buf*4) + mg*2 + 1)*5 + kt)*512 + l*16);
#pragma unroll
            for (int sb = 0; sb < 2; sb++) {
                const int nb = ng * 2 + sb;
                uint4 b4 = *(const uint4*)(smem + SO_B4 + (size_t)((nb*4 + kt))*512 + l*16);
                hmma(acc[0][2][sb], a0, b4.x, b4.y);
                hmma(acc[0][2][sb], a0, b4.z, b4.w);
                hmma(acc[1][2][sb], a1, b4.x, b4.y);
                hmma(acc[1][2][sb], a1, b4.z, b4.w);
                uint4 brz = *(const uint4*)(smem + SO_B2RZ + (size_t)((nb*4 + kt))*512 + l*16);
                hmma(acc[0][0][sb], a0, brz.x, brz.y);
                hmma(acc[1][0][sb], a1, brz.x, brz.y);
                hmma(acc[0][1][sb], a0, brz.z, brz.w);
                hmma(acc[1][1][sb], a1, brz.z, brz.w);
            }
        }
        // ---- kt4: x,bias via m16n8k8 (k0..7 cover all nonzeros) ------------
        {
            uint2 a0 = *(const uint2*)(smem + SO_A + (size_t)(((buf*4) + mg*2 + 0)*5 + 4)*512 + l*16);
            uint2 a1 = *(const uint2*)(smem + SO_A + (size_t)(((buf*4) + mg*2 + 1)*5 + 4)*512 + l*16);
#pragma unroll
            for (int sb = 0; sb < 2; sb++) {
                const int nb = ng * 2 + sb;
                uint2 brz = *(const uint2*)(smem + SO_BK2RZ + (size_t)nb*256 + l*8);
                hmma8(acc[0][0][sb], a0.x, a0.y, brz.x);
                hmma8(acc[1][0][sb], a1.x, a1.y, brz.x);
                hmma8(acc[0][1][sb], a0.x, a0.y, brz.y);
                hmma8(acc[1][1][sb], a1.x, a1.y, brz.y);
                uint2 b4 = *(const uint2*)(smem + SO_BK4 + (size_t)nb*256 + l*8);
                hmma8(acc[0][3][sb], a0.x, a0.y, b4.x);
                hmma8(acc[0][3][sb], a0.x, a0.y, b4.y);
                hmma8(acc[1][3][sb], a1.x, a1.y, b4.x);
                hmma8(acc[1][3][sb], a1.x, a1.y, b4.y);
            }
        }

        // ---- epilogue: gate math + fp16 h STS.128 per mt --------------------
#pragma unroll
        for (int mt = 0; mt < 2; mt++) {
            uint32_t hw[4];
#pragma unroll
            for (int sb = 0; sb < 2; sb++)
#pragma unroll
            for (int rh = 0; rh < 2; rh++) {
                const int rg = rh * 2;
                float r0 = siga(acc[mt][0][sb][rg]);
                float z0 = siga(acc[mt][1][sb][rg]);
                float c0 = tanha(fmaf(r0, acc[mt][2][sb][rg] + bhn[sb][0], acc[mt][3][sb][rg]));
                float h0 = fmaf(z0, hprev[mt][rh][sb][0] - c0, c0);
                float r1 = siga(acc[mt][0][sb][rg+1]);
                float z1 = siga(acc[mt][1][sb][rg+1]);
                float c1 = tanha(fmaf(r1, acc[mt][2][sb][rg+1] + bhn[sb][1], acc[mt][3][sb][rg+1]));
                float h1 = fmaf(z1, hprev[mt][rh][sb][1] - c1, c1);
                hprev[mt][rh][sb][0] = h0;
                hprev[mt][rh][sb][1] = h1;
                hw[rh + 2 * sb] = h2bits(h0, h1);

                if (t == NT - 1) {
                    const int m  = mg * 32 + mt * 16 + rh * 8 + lr;
                    const int j0 = ng * 16 + sb * 8 + 2 * c4;
                    float2 hv; hv.x = h0; hv.y = h1;
                    *(float2*)(&g_hidden[(size_t)(seq0 + m) * NH + j0]) = hv;
                }
            }
            uint4 v; v.x = hw[0]; v.y = hw[1]; v.z = hw[2]; v.w = hw[3];
            *(uint4*)(smem + SO_A + (size_t)(((bufn*4) + mg*2 + mt)*5 + ng)*512 + l*16) = v;
        }

        if (stage) {
            int m = mg * 32 + gtid;
            int mtile = m >> 4, r = m & 15;
            char* base = smem + SO_A + (size_t)((bufn * 4 + mtile) * 5 + 4) * 512
                       + ((r & 7) * 4) * 16 + (r >> 3) * 4;
            *(uint32_t*)(base)      = h2bits(xs[0], xs[1]);
            *(uint32_t*)(base + 16) = h2bits(xs[2], xs[3]);
            *(uint32_t*)(base + 32) = h2bits(1.0f, 0.0f);
        }
        asm volatile("bar.sync %0, 128;" :: "r"(1 + mg) : "memory");
    }
}

// ---------------------------------------------------------------------------
// Kernel 3: lane MLP + phase competition head (R12's proven version).
// ---------------------------------------------------------------------------
__global__ void __launch_bounds__(256)
post_kernel(const float* __restrict__ feat,
            const float* __restrict__ emb_phase,
            const float* __restrict__ Wv,  const float* __restrict__ bv,
            const float* __restrict__ Wl,  const float* __restrict__ bl,
            const float* __restrict__ Wcf, const float* __restrict__ bcf,
            const float* __restrict__ Wcm, const float* __restrict__ bcm,
            const float* __restrict__ Wfin,const float* __restrict__ bfin,
            float* __restrict__ out)
{
    __shared__ float s_hid[4][NL][NH];
    __shared__ float s_lf[4][NL][8];
    __shared__ float s_line[4][NL][16];
    __shared__ float s_pp[4][NL][16];
    __shared__ float s_Wl[16 * 72];
    __shared__ float s_yc[NL * 7 * 20];
    __shared__ float s_val[4][NL][7];

    const int tid = threadIdx.x;
    const int sub = tid >> 6;          // 0..3
    const int st  = tid & 63;
    const int b   = blockIdx.x * 4 + sub;

    for (int i = tid; i < 16 * 72; i += 256) s_Wl[i] = Wl[i];
    for (int i = tid; i < NL * 7 * 20; i += 256) s_yc[i] = g_yc[i];
    for (int i = st; i < NL * NH; i += 64)
        s_hid[sub][i >> 6][i & 63] = g_hidden[(size_t)b * (NL * NH) + i];

    {
        int l = st >> 3, f = st & 7;
        if (f < 4) {
            float vr = feat[b * 16 + 8 + l];
            s_lf[sub][l][f] = sigf(fmaf(vr, Wv[f], bv[f]));
        } else {
            int c = f - 4;
            int pid = (int)feat[b * 16 + l];
            s_lf[sub][l][f] = sigf(emb_phase[pid * 4 + c]);
        }
    }
    __syncthreads();

    for (int i = st; i < NL * 16; i += 64) {
        int l = i >> 4, o = i & 15;
        const float* wrow = &s_Wl[o * 72];
        float v = bl[o];
#pragma unroll
        for (int c = 0; c < 8; c++)  v = fmaf(s_lf[sub][l][c], wrow[c], v);
#pragma unroll
        for (int k = 0; k < NH; k++) v = fmaf(s_hid[sub][l][k], wrow[8 + k], v);
        s_line[sub][l][o] = fmaxf(v, 0.0f);
    }
    __syncthreads();

    for (int i = st; i < NL * 16; i += 64) {
        int p = i >> 4, o = i & 15;
        s_pp[sub][p][o] = s_line[sub][c_PL[p][0]][o] + s_line[sub][c_PL[p][1]][o];
    }
    __syncthreads();

    if (st < 56) {
        int p = st / 7, qi = st % 7;
        int jq = (qi < p) ? qi : qi + 1;

        float xf[20];
#pragma unroll
        for (int o = 0; o < 20; o++) {
            const float* wc = Wcf + o * 32;
            float v = bcf[o];
#pragma unroll
            for (int c = 0; c < 16; c++) v = fmaf(s_pp[sub][p][c],  wc[c],      v);
#pragma unroll
            for (int c = 0; c < 16; c++) v = fmaf(s_pp[sub][jq][c], wc[16 + c], v);
            xf[o] = fmaxf(v, 0.0f) * s_yc[(p * 7 + qi) * 20 + o];
        }
        float val = bfin[0];
#pragma unroll
        for (int o = 0; o < 20; o++) {
            const float* wm = Wcm + o * 20;
            float v = bcm[o];
#pragma unroll
            for (int c = 0; c < 20; c++) v = fmaf(xf[c], wm[c], v);
            val = fmaf(fmaxf(v, 0.0f), Wfin[o], val);
        }
        s_val[sub][p][qi] = val;
    }
    __syncthreads();

    if (st < NL) {
        float acc = 0.0f;
#pragma unroll
        for (int q = 0; q < 7; q++) acc += s_val[sub][st][q];
        out[b * NL + st] = acc;
    }
}

// ---------------------------------------------------------------------------
// Launch
// ---------------------------------------------------------------------------
extern "C" void kernel_launch(void* const* d_in, const int* in_sizes, int n_in,
                              void* d_out, int out_size)
{
    const float* feature  = (const float*)d_in[0];
    const float* history  = (const float*)d_in[1];
    const int*   relation = (const int*)  d_in[2];
    const float* emb_phase= (const float*)d_in[3];
    const float* Wv       = (const float*)d_in[4];
    const float* bv       = (const float*)d_in[5];
    const float* Wh       = (const float*)d_in[6];
    const float* bh       = (const float*)d_in[7];
    const float* Wih      = (const float*)d_in[8];
    const float* Whh      = (const float*)d_in[9];
    const float* bih      = (const float*)d_in[10];
    const float* bhh      = (const float*)d_in[11];
    const float* Wl       = (const float*)d_in[12];
    const float* bl       = (const float*)d_in[13];
    const float* emb_const= (const float*)d_in[14];
    const float* Wcf      = (const float*)d_in[15];
    const float* bcf      = (const float*)d_in[16];
    const float* Wcc      = (const float*)d_in[17];
    const float* bcc      = (const float*)d_in[18];
    const float* Wcm      = (const float*)d_in[19];
    const float* bcm      = (const float*)d_in[20];
    const float* Wfin     = (const float*)d_in[21];
    const float* bfin     = (const float*)d_in[22];
    float* out = (float*)d_out;

    cudaFuncSetAttribute(gru_kernel, cudaFuncAttributeMaxDynamicSharedMemorySize, SMEMSZ);

    build_tables<<<21, 256>>>(Wih, Whh, bih, bhh, relation, emb_const, Wcc, bcc);
    gru_kernel<<<GCTA, GT, SMEMSZ>>>(history, Wh, bh, bhh);
    post_kernel<<<NB / 4, 256>>>(feature, emb_phase, Wv, bv, Wl, bl,
                                 Wcf, bcf, Wcm, bcm, Wfin, bfin, out);
}